// round 14
// baseline (speedup 1.0000x reference)
#include <cuda_runtime.h>

#define DIM    128
#define LMAX   20
#define WPB    8       // warps per block; 1 element per warp -> 8 elements/CTA
#define MAXCTA 4096

__device__ float        g_accum   = 0.0f;   // rearmed to 0 at end of each run
__device__ unsigned int g_counter = 0;

// float4 global load with 256B L2 fetch-granule hint
__device__ __forceinline__ float4 ldg_256b(const float4* p) {
    float4 v;
    asm volatile("ld.global.nc.L2::256B.v4.f32 {%0,%1,%2,%3}, [%4];"
                 : "=f"(v.x), "=f"(v.y), "=f"(v.z), "=f"(v.w)
                 : "l"(p));
    return v;
}

__global__ void __launch_bounds__(256) sg_loss_kernel(
    const float* __restrict__ W0,
    const float* __restrict__ W1,
    const int* __restrict__ target,
    const int* __restrict__ context,
    const int* __restrict__ codes,
    const int* __restrict__ lengths,
    float* __restrict__ out,
    int B, int n_nodes)
{
    const int lane  = threadIdx.x & 31;
    const int wid   = threadIdx.x >> 5;
    const int gwarp = blockIdx.x * WPB + wid;   // one batch element per warp

    float acc = 0.0f;

    if (gwarp < B) {
        // ---- small loads first (independent misses, off the row-gather chain) ----
        const int t   = target[gwarp];          // broadcast
        const int c   = context[gwarp];
        const int len = lengths[gwarp];
        const int code = (lane < LMAX) ? codes[gwarp * LMAX + lane] : 0;

        const bool ok = (unsigned)t < (unsigned)n_nodes &&
                        (unsigned)c < (unsigned)n_nodes;
        const long long ti = ok ? (long long)t : 0;
        const long long ci = ok ? (long long)c : 0;

        // ---- two 512B row gathers, back-to-back ----
        const float4 a = ldg_256b(reinterpret_cast<const float4*>(W0 + ti * DIM) + lane);
        const float4 b = ldg_256b(reinterpret_cast<const float4*>(W1 + ci * DIM) + lane);

        float dot = a.x * b.x + a.y * b.y + a.z * b.z + a.w * b.w;
        #pragma unroll
        for (int o = 16; o > 0; o >>= 1)
            dot += __shfl_xor_sync(0xffffffffu, dot, o);
        // all lanes hold full dot; lanes 0..len-1 evaluate tree levels
        if (ok && lane < len) {
            const float sign = 1.0f - 2.0f * (float)code;
            const float x = sign * dot;
            // stable log_sigmoid: min(x,0) - log1p(exp(-|x|))
            acc = -(fminf(x, 0.0f) - log1pf(__expf(-fabsf(x))));
        }
    }

    // ---- warp + block reduce, one atomic per CTA ----
    #pragma unroll
    for (int o = 16; o > 0; o >>= 1)
        acc += __shfl_xor_sync(0xffffffffu, acc, o);

    __shared__ float smem[WPB];
    __shared__ bool  is_last;
    if (lane == 0) smem[wid] = acc;
    __syncthreads();
    if (threadIdx.x == 0) {
        float s = 0.0f;
        #pragma unroll
        for (int i = 0; i < WPB; ++i) s += smem[i];
        atomicAdd(&g_accum, s);
        __threadfence();
        is_last = (atomicAdd(&g_counter, 1u) == gridDim.x - 1);
    }
    __syncthreads();

    // ---- last CTA: publish + rearm (graph-replay idempotent) ----
    if (is_last && threadIdx.x == 0) {
        __threadfence();
        out[0]    = g_accum;
        g_accum   = 0.0f;
        g_counter = 0;
    }
}

extern "C" void kernel_launch(void* const* d_in, const int* in_sizes, int n_in,
                              void* d_out, int out_size)
{
    const float* W0      = (const float*)d_in[0];
    const float* W1      = (const float*)d_in[1];
    const int*   target  = (const int*)d_in[2];
    const int*   context = (const int*)d_in[3];
    const int*   codes   = (const int*)d_in[4];
    const int*   lengths = (const int*)d_in[5];
    float* out = (float*)d_out;

    const int B = in_sizes[2];                 // 16384
    const int n_nodes = in_sizes[0] / DIM;     // 1,000,000
    int blocks = (B + WPB - 1) / WPB;          // 2048
    if (blocks > MAXCTA) blocks = MAXCTA;

    sg_loss_kernel<<<blocks, 256>>>(W0, W1, target, context, codes, lengths, out, B, n_nodes);
}

// round 15
// speedup vs baseline: 1.0774x; 1.0774x over previous
#include <cuda_runtime.h>

#define DIM   128
#define LMAX  20
#define EPW   2      // elements per warp
#define WPB   8      // warps per block -> 16 elements per CTA
#define MAXCTA 2048

__device__ float        g_partials[MAXCTA];
__device__ unsigned int g_counter = 0;

// float4 global load pinned to L2 with evict_last policy (retain across graph replays)
__device__ __forceinline__ float4 ldg_persist(const float4* p) {
    float4 v;
    asm volatile(
        "{\n\t"
        ".reg .b64 pol;\n\t"
        "createpolicy.fractional.L2::evict_last.b64 pol, 1.0;\n\t"
        "ld.global.nc.L2::cache_hint.v4.f32 {%0,%1,%2,%3}, [%4], pol;\n\t"
        "}"
        : "=f"(v.x), "=f"(v.y), "=f"(v.z), "=f"(v.w)
        : "l"(p));
    return v;
}

__global__ void __launch_bounds__(256) sg_loss_kernel(
    const float* __restrict__ W0,
    const float* __restrict__ W1,
    const int* __restrict__ target,
    const int* __restrict__ context,
    const int* __restrict__ codes,
    const int* __restrict__ lengths,
    float* __restrict__ out,
    int B, int n_nodes)
{
    const int lane = threadIdx.x & 31;
    const int wid  = threadIdx.x >> 5;
    const int base = (blockIdx.x * WPB + wid) * EPW;

    float acc = 0.0f;

    if (base < B) {
        // ---- hoist ALL small loads: indices, lengths, codes ----
        int t[EPW], c[EPW], len[EPW], code[EPW];
        #pragma unroll
        for (int e = 0; e < EPW; ++e) {
            const int i = base + e;
            const bool inb = (i < B);
            t[e]    = inb ? target[i]  : 0;
            c[e]    = inb ? context[i] : 0;
            len[e]  = inb ? lengths[i] : 0;
            code[e] = (inb && lane < LMAX) ? codes[i * LMAX + lane] : 0;
        }

        // ---- 4 row gathers back-to-back, L2 evict_last (persist across replays) ----
        float4 a[EPW], b[EPW];
        #pragma unroll
        for (int e = 0; e < EPW; ++e) {
            const bool ok = (base + e < B) &&
                            (unsigned)t[e] < (unsigned)n_nodes &&
                            (unsigned)c[e] < (unsigned)n_nodes;
            const long long ti = ok ? (long long)t[e] : 0;
            const long long ci = ok ? (long long)c[e] : 0;
            a[e] = ldg_persist(reinterpret_cast<const float4*>(W0 + ti * DIM) + lane);
            b[e] = ldg_persist(reinterpret_cast<const float4*>(W1 + ci * DIM) + lane);
            if (!ok) len[e] = 0;
        }

        // ---- dot + log-sigmoid levels ----
        #pragma unroll
        for (int e = 0; e < EPW; ++e) {
            float dot = a[e].x * b[e].x + a[e].y * b[e].y
                      + a[e].z * b[e].z + a[e].w * b[e].w;
            #pragma unroll
            for (int o = 16; o > 0; o >>= 1)
                dot += __shfl_xor_sync(0xffffffffu, dot, o);
            if (lane < len[e]) {
                const float sign = 1.0f - 2.0f * (float)code[e];
                const float x = sign * dot;
                // stable log_sigmoid: min(x,0) - log1p(exp(-|x|))
                acc -= fminf(x, 0.0f) - log1pf(__expf(-fabsf(x)));
            }
        }
    }

    // ---- warp + block reduce ----
    #pragma unroll
    for (int o = 16; o > 0; o >>= 1)
        acc += __shfl_xor_sync(0xffffffffu, acc, o);

    __shared__ float smem[WPB];
    __shared__ bool  is_last;
    if (lane == 0) smem[wid] = acc;
    __syncthreads();
    if (threadIdx.x == 0) {
        float s = 0.0f;
        #pragma unroll
        for (int i = 0; i < WPB; ++i) s += smem[i];
        g_partials[blockIdx.x] = s;
        __threadfence();
        is_last = (atomicAdd(&g_counter, 1u) == gridDim.x - 1);
    }
    __syncthreads();

    // ---- last CTA: fixed-order final reduce (deterministic) ----
    if (is_last) {
        __threadfence();
        const int nb = gridDim.x;
        float v = 0.0f;
        for (int i = threadIdx.x; i < nb; i += blockDim.x)
            v += g_partials[i];
        #pragma unroll
        for (int o = 16; o > 0; o >>= 1)
            v += __shfl_xor_sync(0xffffffffu, v, o);
        __shared__ float smem2[WPB];
        if (lane == 0) smem2[wid] = v;
        __syncthreads();
        if (threadIdx.x == 0) {
            float s = 0.0f;
            #pragma unroll
            for (int i = 0; i < WPB; ++i) s += smem2[i];
            out[0] = s;
            g_counter = 0;   // reset for next graph replay
        }
    }
}

extern "C" void kernel_launch(void* const* d_in, const int* in_sizes, int n_in,
                              void* d_out, int out_size)
{
    const float* W0      = (const float*)d_in[0];
    const float* W1      = (const float*)d_in[1];
    const int*   target  = (const int*)d_in[2];
    const int*   context = (const int*)d_in[3];
    const int*   codes   = (const int*)d_in[4];
    const int*   lengths = (const int*)d_in[5];
    float* out = (float*)d_out;

    const int B = in_sizes[2];                 // 16384
    const int n_nodes = in_sizes[0] / DIM;     // 1,000,000
    const int epc = WPB * EPW;                 // 16 elements per CTA
    int blocks = (B + epc - 1) / epc;          // 1024
    if (blocks > MAXCTA) blocks = MAXCTA;

    sg_loss_kernel<<<blocks, 256>>>(W0, W1, target, context, codes, lengths, out, B, n_nodes);
}

// round 16
// speedup vs baseline: 1.0904x; 1.0120x over previous
#include <cuda_runtime.h>

#define DIM   128
#define LMAX  20
#define EPW   2      // elements per warp
#define WPB   8      // warps per block -> 16 elements per CTA
#define MAXCTA 2048

__device__ float        g_partials[MAXCTA];
__device__ unsigned int g_counter = 0;

// float4 global load with 256B L2 fetch-granule hint
__device__ __forceinline__ float4 ldg_256b(const float4* p) {
    float4 v;
    asm volatile("ld.global.nc.L2::256B.v4.f32 {%0,%1,%2,%3}, [%4];"
                 : "=f"(v.x), "=f"(v.y), "=f"(v.z), "=f"(v.w)
                 : "l"(p));
    return v;
}

__global__ void __launch_bounds__(256) sg_loss_kernel(
    const float* __restrict__ W0,
    const float* __restrict__ W1,
    const int* __restrict__ target,
    const int* __restrict__ context,
    const int* __restrict__ codes,
    const int* __restrict__ lengths,
    float* __restrict__ out,
    int B, int n_nodes)
{
    const int lane = threadIdx.x & 31;
    const int wid  = threadIdx.x >> 5;
    const int base = (blockIdx.x * WPB + wid) * EPW;

    float acc = 0.0f;

    if (base < B) {
        // ---- hoist ALL small loads: indices, lengths, codes (independent misses) ----
        int t[EPW], c[EPW], len[EPW], code[EPW];
        #pragma unroll
        for (int e = 0; e < EPW; ++e) {
            const int i = base + e;
            const bool inb = (i < B);
            t[e]    = inb ? target[i]  : 0;
            c[e]    = inb ? context[i] : 0;
            len[e]  = inb ? lengths[i] : 0;
            code[e] = (inb && lane < LMAX) ? codes[i * LMAX + lane] : 0;
        }

        // ---- 4 row gathers back-to-back, 256B L2 fetch granule ----
        float4 a[EPW], b[EPW];
        #pragma unroll
        for (int e = 0; e < EPW; ++e) {
            const bool ok = (base + e < B) &&
                            (unsigned)t[e] < (unsigned)n_nodes &&
                            (unsigned)c[e] < (unsigned)n_nodes;
            const long long ti = ok ? (long long)t[e] : 0;
            const long long ci = ok ? (long long)c[e] : 0;
            a[e] = ldg_256b(reinterpret_cast<const float4*>(W0 + ti * DIM) + lane);
            b[e] = ldg_256b(reinterpret_cast<const float4*>(W1 + ci * DIM) + lane);
            if (!ok) len[e] = 0;
        }

        // ---- dot + log-sigmoid tree levels ----
        #pragma unroll
        for (int e = 0; e < EPW; ++e) {
            float dot = a[e].x * b[e].x + a[e].y * b[e].y
                      + a[e].z * b[e].z + a[e].w * b[e].w;
            #pragma unroll
            for (int o = 16; o > 0; o >>= 1)
                dot += __shfl_xor_sync(0xffffffffu, dot, o);
            // all lanes hold full dot; lanes 0..len-1 evaluate levels
            if (lane < len[e]) {
                const float sign = 1.0f - 2.0f * (float)code[e];
                const float x = sign * dot;
                // stable log_sigmoid: min(x,0) - log1p(exp(-|x|))
                acc -= fminf(x, 0.0f) - log1pf(__expf(-fabsf(x)));
            }
        }
    }

    // ---- warp + block reduce ----
    #pragma unroll
    for (int o = 16; o > 0; o >>= 1)
        acc += __shfl_xor_sync(0xffffffffu, acc, o);

    __shared__ float smem[WPB];
    __shared__ bool  is_last;
    if (lane == 0) smem[wid] = acc;
    __syncthreads();
    if (threadIdx.x == 0) {
        float s = 0.0f;
        #pragma unroll
        for (int i = 0; i < WPB; ++i) s += smem[i];
        g_partials[blockIdx.x] = s;
        __threadfence();
        is_last = (atomicAdd(&g_counter, 1u) == gridDim.x - 1);
    }
    __syncthreads();

    // ---- last CTA: fixed-order final reduce (deterministic), rearm counter ----
    if (is_last) {
        __threadfence();
        const int nb = gridDim.x;
        float v = 0.0f;
        for (int i = threadIdx.x; i < nb; i += blockDim.x)
            v += g_partials[i];
        #pragma unroll
        for (int o = 16; o > 0; o >>= 1)
            v += __shfl_xor_sync(0xffffffffu, v, o);
        __shared__ float smem2[WPB];
        if (lane == 0) smem2[wid] = v;
        __syncthreads();
        if (threadIdx.x == 0) {
            float s = 0.0f;
            #pragma unroll
            for (int i = 0; i < WPB; ++i) s += smem2[i];
            out[0] = s;
            g_counter = 0;   // reset for next graph replay
        }
    }
}

extern "C" void kernel_launch(void* const* d_in, const int* in_sizes, int n_in,
                              void* d_out, int out_size)
{
    const float* W0      = (const float*)d_in[0];
    const float* W1      = (const float*)d_in[1];
    const int*   target  = (const int*)d_in[2];
    const int*   context = (const int*)d_in[3];
    const int*   codes   = (const int*)d_in[4];
    const int*   lengths = (const int*)d_in[5];
    float* out = (float*)d_out;

    const int B = in_sizes[2];                 // 16384
    const int n_nodes = in_sizes[0] / DIM;     // 1,000,000
    const int epc = WPB * EPW;                 // 16 elements per CTA
    int blocks = (B + epc - 1) / epc;          // 1024
    if (blocks > MAXCTA) blocks = MAXCTA;

    sg_loss_kernel<<<blocks, 256>>>(W0, W1, target, context, codes, lengths, out, B, n_nodes);
}

// round 17
// speedup vs baseline: 1.1529x; 1.0573x over previous
#include <cuda_runtime.h>

#define DIM   128
#define LMAX  20
#define EPW   2       // elements per warp
#define WPB   16      // warps per block (512 threads) -> 32 elements per CTA
#define NTHR  (WPB * 32)
#define MAXCTA 1024

__device__ float        g_partials[MAXCTA];
__device__ unsigned int g_counter = 0;

// float4 global load with 256B L2 fetch-granule hint
__device__ __forceinline__ float4 ldg_256b(const float4* p) {
    float4 v;
    asm volatile("ld.global.nc.L2::256B.v4.f32 {%0,%1,%2,%3}, [%4];"
                 : "=f"(v.x), "=f"(v.y), "=f"(v.z), "=f"(v.w)
                 : "l"(p));
    return v;
}

__global__ void __launch_bounds__(NTHR) sg_loss_kernel(
    const float* __restrict__ W0,
    const float* __restrict__ W1,
    const int* __restrict__ target,
    const int* __restrict__ context,
    const int* __restrict__ codes,
    const int* __restrict__ lengths,
    float* __restrict__ out,
    int B, int n_nodes)
{
    const int lane = threadIdx.x & 31;
    const int wid  = threadIdx.x >> 5;
    const int base = (blockIdx.x * WPB + wid) * EPW;

    float acc = 0.0f;

    if (base < B) {
        // ---- hoist ALL small loads: indices, lengths, codes (independent misses) ----
        int t[EPW], c[EPW], len[EPW], code[EPW];
        #pragma unroll
        for (int e = 0; e < EPW; ++e) {
            const int i = base + e;
            const bool inb = (i < B);
            t[e]    = inb ? target[i]  : 0;
            c[e]    = inb ? context[i] : 0;
            len[e]  = inb ? lengths[i] : 0;
            code[e] = (inb && lane < LMAX) ? codes[i * LMAX + lane] : 0;
        }

        // ---- 4 row gathers back-to-back, 256B L2 fetch granule ----
        float4 a[EPW], b[EPW];
        #pragma unroll
        for (int e = 0; e < EPW; ++e) {
            const bool ok = (base + e < B) &&
                            (unsigned)t[e] < (unsigned)n_nodes &&
                            (unsigned)c[e] < (unsigned)n_nodes;
            const long long ti = ok ? (long long)t[e] : 0;
            const long long ci = ok ? (long long)c[e] : 0;
            a[e] = ldg_256b(reinterpret_cast<const float4*>(W0 + ti * DIM) + lane);
            b[e] = ldg_256b(reinterpret_cast<const float4*>(W1 + ci * DIM) + lane);
            if (!ok) len[e] = 0;
        }

        // ---- dot + log-sigmoid tree levels ----
        #pragma unroll
        for (int e = 0; e < EPW; ++e) {
            float dot = a[e].x * b[e].x + a[e].y * b[e].y
                      + a[e].z * b[e].z + a[e].w * b[e].w;
            #pragma unroll
            for (int o = 16; o > 0; o >>= 1)
                dot += __shfl_xor_sync(0xffffffffu, dot, o);
            // all lanes hold full dot; lanes 0..len-1 evaluate levels
            if (lane < len[e]) {
                const float sign = 1.0f - 2.0f * (float)code[e];
                const float x = sign * dot;
                // stable log_sigmoid: min(x,0) - log1p(exp(-|x|))
                acc -= fminf(x, 0.0f) - log1pf(__expf(-fabsf(x)));
            }
        }
    }

    // ---- warp + block reduce ----
    #pragma unroll
    for (int o = 16; o > 0; o >>= 1)
        acc += __shfl_xor_sync(0xffffffffu, acc, o);

    __shared__ float smem[WPB];
    __shared__ bool  is_last;
    if (lane == 0) smem[wid] = acc;
    __syncthreads();
    if (threadIdx.x == 0) {
        float s = 0.0f;
        #pragma unroll
        for (int i = 0; i < WPB; ++i) s += smem[i];
        g_partials[blockIdx.x] = s;
        __threadfence();
        is_last = (atomicAdd(&g_counter, 1u) == gridDim.x - 1);
    }
    __syncthreads();

    // ---- last CTA: fixed-order final reduce (deterministic), rearm counter ----
    if (is_last) {
        __threadfence();
        const int nb = gridDim.x;
        float v = 0.0f;
        for (int i = threadIdx.x; i < nb; i += blockDim.x)
            v += g_partials[i];
        #pragma unroll
        for (int o = 16; o > 0; o >>= 1)
            v += __shfl_xor_sync(0xffffffffu, v, o);
        __shared__ float smem2[WPB];
        if (lane == 0) smem2[wid] = v;
        __syncthreads();
        if (threadIdx.x == 0) {
            float s = 0.0f;
            #pragma unroll
            for (int i = 0; i < WPB; ++i) s += smem2[i];
            out[0] = s;
            g_counter = 0;   // reset for next graph replay
        }
    }
}

extern "C" void kernel_launch(void* const* d_in, const int* in_sizes, int n_in,
                              void* d_out, int out_size)
{
    const float* W0      = (const float*)d_in[0];
    const float* W1      = (const float*)d_in[1];
    const int*   target  = (const int*)d_in[2];
    const int*   context = (const int*)d_in[3];
    const int*   codes   = (const int*)d_in[4];
    const int*   lengths = (const int*)d_in[5];
    float* out = (float*)d_out;

    const int B = in_sizes[2];                 // 16384
    const int n_nodes = in_sizes[0] / DIM;     // 1,000,000
    const int epc = WPB * EPW;                 // 32 elements per CTA
    int blocks = (B + epc - 1) / epc;          // 512
    if (blocks > MAXCTA) blocks = MAXCTA;

    sg_loss_kernel<<<blocks, NTHR>>>(W0, W1, target, context, codes, lengths, out, B, n_nodes);
}